// round 4
// baseline (speedup 1.0000x reference)
#include <cuda_runtime.h>
#include <cstdint>

typedef unsigned long long U64;
typedef unsigned int U32;

#define NLINES (512*512)
#define NVOX   (512*512*48)
#define MCL    4096
#define NREP   32                  // replicated global accumulator tables

// -------- scratch (static device globals; zero-initialized at load) --------
__device__ U64  g_tab[NREP * MCL]; // packed: [0:18) s0  [18:36) s1  [36:54) s2  [54:64) cnt
__device__ U64  g_keys[MCL];       // (count+1 or 0)<<12 | (4095-idx)
__device__ float g_bs[MCL*4];      // boxes (float4)

// ============ 1: fused erode(k,j,i) + hash + REDG accumulate ============
// Tile: 32x32 lines (i,j), halo 4 -> 40x40 k-eroded words in smem.
__global__ void __launch_bounds__(512, 2) k_main(const float* __restrict__ pm,
                                                 const float* __restrict__ emb) {
    __shared__ U64 sA[40][41];   // k-eroded, rows i0-4..i0+35, cols j0-4..j0+35
    __shared__ U64 sB[40][33];   // j-eroded, cols j0..j0+31

    const int i0 = blockIdx.y * 32, j0 = blockIdx.x * 32;
    const int t = threadIdx.x;   // 512 threads
    const int bid = blockIdx.y * 16 + blockIdx.x;
    U64* tab = g_tab + (size_t)(bid & (NREP - 1)) * MCL;

    // phase 1: binarize + k-erode halo lines
    for (int p = t; p < 40 * 40; p += 512) {
        int r = p / 40, c = p - r * 40;
        int i = i0 + r - 4, j = j0 + c - 4;
        U64 v = 0ULL;
        if ((unsigned)i < 512u && (unsigned)j < 512u) {
            const float4* q = reinterpret_cast<const float4*>(pm) +
                              (size_t)(i * 512 + j) * 12;
            U64 b = 0ULL;
#pragma unroll
            for (int w = 0; w < 12; w++) {
                float4 f = __ldg(q + w);
                U64 nib = (U64)((f.x > 0.5f) | ((f.y > 0.5f) << 1) |
                                ((f.z > 0.5f) << 2) | ((f.w > 0.5f) << 3));
                b |= nib << (w * 4);
            }
            v = b;
#pragma unroll
            for (int s = 1; s <= 4; s++) v &= (b >> s) & (b << s);
        }
        sA[r][c] = v;
    }
    __syncthreads();

    // phase 2: erode along j
    for (int p = t; p < 40 * 32; p += 512) {
        int r = p >> 5, c = p & 31;
        U64 v = sA[r][c];
#pragma unroll
        for (int d = 1; d <= 8; d++) v &= sA[r][c + d];
        sB[r][c] = v;
    }
    __syncthreads();

    // phase 3: erode along i -> final mask into sA[r][c] (32x32)
    for (int p = t; p < 32 * 32; p += 512) {
        int r = p >> 5, c = p & 31;
        U64 v = sB[r][c];
#pragma unroll
        for (int d = 1; d <= 8; d++) v &= sB[r + d][c];
        sA[r][c] = v;
    }
    __syncthreads();

    // phase 4: accumulate this tile's voxels (12 groups of 4 per line)
    const float4* p0 = reinterpret_cast<const float4*>(emb);
    const float4* p1 = p0 + (NVOX / 4);
    const float4* p2 = p1 + (NVOX / 4);
    for (int p = t; p < 32 * 32 * 12; p += 512) {
        int grp = p % 12;
        int lin = p / 12;
        int r = lin >> 5, c = lin & 31;
        U32 mb = (U32)((sA[r][c] >> (grp * 4)) & 0xFULL);
        if (!mb) continue;
        size_t g = (size_t)((i0 + r) * 512 + (j0 + c)) * 12 + grp;
        float4 ex = __ldg(p0 + g);
        float4 ey = __ldg(p1 + g);
        float4 ez = __ldg(p2 + g);
        float X[4] = {ex.x, ex.y, ex.z, ex.w};
        float Y[4] = {ey.x, ey.y, ey.z, ey.w};
        float Z[4] = {ez.x, ez.y, ez.z, ez.w};
#pragma unroll
        for (int v = 0; v < 4; v++) {
            if (!((mb >> v) & 1u)) continue;
            float a = X[v], b = Y[v], cc = Z[v];
            if (!(a > -2.0f || b > -2.0f || cc > -2.0f)) continue;
            float c0 = rintf(a * 25.0f);
            float c1 = rintf(b * 25.0f);
            float c2 = rintf(cc * 25.0f);
            U32 q0 = (U32)fminf(fmaxf(c0 + 128.0f, 0.0f), 255.0f);
            U32 q1 = (U32)fminf(fmaxf(c1 + 128.0f, 0.0f), 255.0f);
            U32 q2 = (U32)fminf(fmaxf(c2 + 128.0f, 0.0f), 255.0f);
            U32 seg = (q0 * 73856093u ^ q1 * 19349663u ^ q2 * 83492791u) & 4095u;
            U64 add = (1ULL << 54)
                    | (U64)(U32)((int)c0 + 256)
                    | ((U64)(U32)((int)c1 + 256) << 18)
                    | ((U64)(U32)((int)c2 + 256) << 36);
            atomicAdd(&tab[seg], add);       // RED.E.ADD.64 (no return)
        }
    }
}

// ============ 2: reduce replicas -> centroids/keys/boxes; self-zero ============
__global__ void k_finalize(float* __restrict__ out) {
    int b = blockIdx.x * blockDim.x + threadIdx.x;
    if (b >= MCL) return;
    int s0 = 0, s1 = 0, s2 = 0;
    U32 cnt = 0;
#pragma unroll 8
    for (int r = 0; r < NREP; r++) {
        U64 v = g_tab[r * MCL + b];
        g_tab[r * MCL + b] = 0ULL;           // restore zero-state for next replay
        U32 c = (U32)(v >> 54);
        cnt += c;
        int bias = (int)c * 256;
        s0 += (int)(v & 0x3FFFFULL) - bias;
        s1 += (int)((v >> 18) & 0x3FFFFULL) - bias;
        s2 += (int)((v >> 36) & 0x3FFFFULL) - bias;
    }
    float d = fmaxf((float)cnt, 1.0f);
    float c0 = (float)s0 / d, c1 = (float)s1 / d, c2 = (float)s2 / d;
    out[b*3+0] = c0; out[b*3+1] = c1; out[b*3+2] = c2;
    g_bs[b*4+0] = c0 - 22.5f;
    g_bs[b*4+1] = c1 - 22.5f;
    g_bs[b*4+2] = c0 + 22.5f;
    g_bs[b*4+3] = c1 + 22.5f;
    U64 c1k = (cnt >= 10u) ? (U64)(cnt + 1u) : 0ULL;
    g_keys[b] = (c1k << 12) | (U64)(4095 - b);
}

// ============ 3: exact greedy NMS via max-key selection (1 block) ============
__global__ void k_nms(float* __restrict__ out, int write_keep) {
    __shared__ U64 sk[MCL];
    __shared__ U64 swarp[8];
    __shared__ U64 sbest;
    int t = threadIdx.x;          // 256 threads; thread t owns idx = t + 256*s
    for (int i = t; i < MCL; i += 256) sk[i] = g_keys[i];
    U32 rm = 0, dn = 0;
    const float4* boxes = reinterpret_cast<const float4*>(g_bs);
    __syncthreads();

    const U64 CLUS = (U64)11 << 12;   // key >= this <=> count >= 10
    while (true) {
        U64 m = 0ULL;
#pragma unroll
        for (int s = 0; s < 16; s++) {
            if (((rm | dn) >> s) & 1u) continue;
            U64 k = sk[t + 256 * s];
            if (k >= CLUS && k > m) m = k;
        }
#pragma unroll
        for (int o = 16; o; o >>= 1) {
            U64 other = __shfl_xor_sync(0xffffffffu, m, o);
            if (other > m) m = other;
        }
        if ((t & 31) == 0) swarp[t >> 5] = m;
        __syncthreads();
        if (t == 0) {
            U64 mm = swarp[0];
#pragma unroll
            for (int w = 1; w < 8; w++) if (swarp[w] > mm) mm = swarp[w];
            sbest = mm;
        }
        __syncthreads();
        U64 best = sbest;
        __syncthreads();
        if (best == 0ULL) break;
        int pivot = 4095 - (int)(best & 4095ULL);
        if ((pivot & 255) == t) dn |= 1u << (pivot >> 8);
        float4 pb = boxes[pivot];
        float pa = (pb.z - pb.x) * (pb.w - pb.y);
#pragma unroll
        for (int s = 0; s < 16; s++) {
            if ((rm >> s) & 1u) continue;
            int idx = t + 256 * s;
            if (sk[idx] >= best) continue;   // only lower-ranked suppressed
            float4 bb = boxes[idx];
            float x1 = fmaxf(pb.x, bb.x), y1 = fmaxf(pb.y, bb.y);
            float x2 = fminf(pb.z, bb.z), y2 = fminf(pb.w, bb.w);
            float inter = fmaxf(x2 - x1, 0.0f) * fmaxf(y2 - y1, 0.0f);
            float a2 = (bb.z - bb.x) * (bb.w - bb.y);
            float iou = inter / fmaxf(pa + a2 - inter, 1e-9f);
            if (iou > 0.5f) rm |= 1u << s;
        }
    }
    if (write_keep) {
#pragma unroll
        for (int s = 0; s < 16; s++) {
            int idx = t + 256 * s;
            bool keep = (sk[idx] >= CLUS) && !((rm >> s) & 1u);
            out[12288 + idx] = keep ? 1.0f : 0.0f;
        }
    }
}

extern "C" void kernel_launch(void* const* d_in, const int* in_sizes, int n_in,
                              void* d_out, int out_size) {
    const float* emb = (const float*)d_in[0];
    const float* pm  = (const float*)d_in[1];
    if (n_in >= 2 && in_sizes[0] == NVOX && in_sizes[1] == 3*NVOX) {
        emb = (const float*)d_in[1];
        pm  = (const float*)d_in[0];
    }
    float* out = (float*)d_out;

    k_main    <<<dim3(16, 16), 512>>>(pm, emb);
    k_finalize<<<16, 256>>>(out);
    k_nms     <<<1, 256>>>(out, (out_size >= 12288 + MCL) ? 1 : 0);
}